// round 4
// baseline (speedup 1.0000x reference)
#include <cuda_runtime.h>
#include <cstdint>

#define N_NODES 5120
#define N_EDGES 163840
#define TBLD    256
#define LAT     128
#define NG      64
#define NN      80
#define N2      6400
#define H1      12800

// ---------------- scratch (no allocs allowed) ----------------
__device__ __align__(128) float g_h [N_NODES * LAT];
__device__ __align__(128) float g_z [N_NODES * LAT];
__device__ __align__(128) float g_z2[NG * N2];
__device__ __align__(128) float g_z3[NG * H1];
__device__ __align__(128) float g_p1[3][NG * H1];   // GEMM1 split-K partials
__device__ __align__(128) float g_p2[6][NG * N2];   // GEMM2 split-K partials
__device__ int   g_deg[N_NODES];
__device__ int   g_cur[N_NODES];
__device__ int   g_row[N_NODES];
__device__ float g_dinv[N_NODES];
__device__ int   g_csr[N_EDGES];

// ---------------- stage 0: clear counters ----------------
__global__ void k_clear() {
    int i = blockIdx.x * blockDim.x + threadIdx.x;
    if (i < N_NODES) { g_deg[i] = 0; g_cur[i] = 0; }
}

// ---------------- stage 1: h = x @ Wg  (5120x256 @ 256x128, fp32) ------------
__global__ void k_xwg(const float* __restrict__ x, const float* __restrict__ Wg) {
    __shared__ float Xs[32][33];
    __shared__ float Ws[32][128];
    int tid = threadIdx.x;
    int m0  = blockIdx.x * 32;
    int tm  = (tid >> 5) * 4;
    int tn  = (tid & 31) * 4;
    float acc[4][4] = {};
    for (int k0 = 0; k0 < TBLD; k0 += 32) {
        int r = tid >> 3, c = (tid & 7) * 4;
        float4 xv = *(const float4*)&x[(m0 + r) * TBLD + k0 + c];
        Xs[r][c] = xv.x; Xs[r][c + 1] = xv.y; Xs[r][c + 2] = xv.z; Xs[r][c + 3] = xv.w;
#pragma unroll
        for (int i = 0; i < 4; i++) {
            int idx = tid + i * 256;
            int wr = idx >> 5, wc = (idx & 31) * 4;
            *(float4*)&Ws[wr][wc] = *(const float4*)&Wg[(k0 + wr) * LAT + wc];
        }
        __syncthreads();
#pragma unroll
        for (int kk = 0; kk < 32; kk++) {
            float a0 = Xs[tm][kk], a1 = Xs[tm + 1][kk], a2 = Xs[tm + 2][kk], a3 = Xs[tm + 3][kk];
            float4 bv = *(float4*)&Ws[kk][tn];
            acc[0][0] += a0 * bv.x; acc[0][1] += a0 * bv.y; acc[0][2] += a0 * bv.z; acc[0][3] += a0 * bv.w;
            acc[1][0] += a1 * bv.x; acc[1][1] += a1 * bv.y; acc[1][2] += a1 * bv.z; acc[1][3] += a1 * bv.w;
            acc[2][0] += a2 * bv.x; acc[2][1] += a2 * bv.y; acc[2][2] += a2 * bv.z; acc[2][3] += a2 * bv.w;
            acc[3][0] += a3 * bv.x; acc[3][1] += a3 * bv.y; acc[3][2] += a3 * bv.z; acc[3][3] += a3 * bv.w;
        }
        __syncthreads();
    }
#pragma unroll
    for (int i = 0; i < 4; i++) {
        float4 v = make_float4(acc[i][0], acc[i][1], acc[i][2], acc[i][3]);
        *(float4*)&g_h[(m0 + tm + i) * LAT + tn] = v;
    }
}

// ---------------- stage 2: degree histogram over dst ----------------
__global__ void k_deg(const int* __restrict__ ei) {
    int e = blockIdx.x * blockDim.x + threadIdx.x;
    if (e < N_EDGES) atomicAdd(&g_deg[ei[N_EDGES + e]], 1);
}

// ---------------- stage 3: exclusive scan -> rowstart, dinv ----------------
__global__ void k_scan() {
    __shared__ int ss[1024];
    int tid = threadIdx.x;
    int base = tid * 5;
    int d[5]; int s = 0;
#pragma unroll
    for (int i = 0; i < 5; i++) { d[i] = g_deg[base + i]; s += d[i]; }
    ss[tid] = s;
    __syncthreads();
    for (int off = 1; off < 1024; off <<= 1) {
        int v = (tid >= off) ? ss[tid - off] : 0;
        __syncthreads();
        ss[tid] += v;
        __syncthreads();
    }
    int pre = (tid > 0) ? ss[tid - 1] : 0;
#pragma unroll
    for (int i = 0; i < 5; i++) {
        g_row[base + i]  = pre;
        pre += d[i];
        g_dinv[base + i] = d[i] > 0 ? rsqrtf((float)d[i]) : 0.f;
    }
}

// ---------------- stage 4: CSR fill (group edges by dst) ----------------
__global__ void k_csr(const int* __restrict__ ei) {
    int e = blockIdx.x * blockDim.x + threadIdx.x;
    if (e < N_EDGES) {
        int s = ei[e];
        int d = ei[N_EDGES + e];
        int p = atomicAdd(&g_cur[d], 1);
        g_csr[g_row[d] + p] = s;
    }
}

// ---------------- stage 5: gather-aggregate + bias + relu ----------------
// one warp per dst node, each lane owns 4 features
__global__ void k_gather(const float* __restrict__ bg) {
    int node = blockIdx.x * 8 + (threadIdx.x >> 5);
    int lane = threadIdx.x & 31;
    int start = g_row[node];
    int cnt   = g_deg[node];
    float dd  = g_dinv[node];
    float4 acc = {0.f, 0.f, 0.f, 0.f};
    const float4* h4 = (const float4*)g_h;
    for (int j = 0; j < cnt; j++) {
        int s  = g_csr[start + j];
        float w = dd * g_dinv[s];
        float4 hv = h4[s * 32 + lane];
        acc.x += w * hv.x; acc.y += w * hv.y; acc.z += w * hv.z; acc.w += w * hv.w;
    }
    float4 bv = ((const float4*)bg)[lane];
    acc.x = fmaxf(acc.x + bv.x, 0.f);
    acc.y = fmaxf(acc.y + bv.y, 0.f);
    acc.z = fmaxf(acc.z + bv.z, 0.f);
    acc.w = fmaxf(acc.w + bv.w, 0.f);
    ((float4*)g_z)[node * 32 + lane] = acc;
}

// ---------------- stage 6: per-graph outer product z z^T ----------------
__global__ void k_outer() {
    __shared__ float Zs[NN][LAT + 1];
    int b = blockIdx.x, tid = threadIdx.x;
#pragma unroll
    for (int i = 0; i < 40; i++) {
        int idx = tid + i * 256;
        Zs[idx >> 7][idx & 127] = g_z[b * NN * LAT + idx];
    }
    __syncthreads();
    int rn = (tid >> 4) * 5;
    int rm = (tid & 15) * 5;
    float acc[5][5] = {};
    for (int l = 0; l < LAT; l++) {
        float a[5], bb[5];
#pragma unroll
        for (int i = 0; i < 5; i++) a[i]  = Zs[rn + i][l];
#pragma unroll
        for (int j = 0; j < 5; j++) bb[j] = Zs[rm + j][l];
#pragma unroll
        for (int i = 0; i < 5; i++)
#pragma unroll
            for (int j = 0; j < 5; j++) acc[i][j] += a[i] * bb[j];
    }
#pragma unroll
    for (int i = 0; i < 5; i++)
#pragma unroll
        for (int j = 0; j < 5; j++)
            g_z2[b * N2 + (rn + i) * NN + (rm + j)] = acc[i][j];
}

// ---------------- big GEMMs: tf32 mma.sync, cp.async pipeline ----------------
__device__ __forceinline__ uint32_t sptr(const void* p) {
    return (uint32_t)__cvta_generic_to_shared(p);
}
__device__ __forceinline__ void cp16(uint32_t s, const void* g) {
    asm volatile("cp.async.cg.shared.global [%0], [%1], 16;" :: "r"(s), "l"(g));
}
__device__ __forceinline__ void mma8(float* c, const uint32_t* a, const uint32_t* b) {
    asm volatile(
        "mma.sync.aligned.m16n8k8.row.col.f32.tf32.tf32.f32 "
        "{%0,%1,%2,%3}, {%4,%5,%6,%7}, {%8,%9}, {%0,%1,%2,%3};"
        : "+f"(c[0]), "+f"(c[1]), "+f"(c[2]), "+f"(c[3])
        : "r"(a[0]), "r"(a[1]), "r"(a[2]), "r"(a[3]), "r"(b[0]), "r"(b[1]));
}

#define MM_S 5  // pipeline stages

// CTA: 64(M) x 128(N) tile, 4 warps in 2x2 grid (warp tile 32x64), k-step = 8
template<int MODE>
__global__ __launch_bounds__(128, 2) void k_mm(const float* __restrict__ W) {
    constexpr int K    = (MODE == 1) ? N2 : H1;
    constexpr int NOUT = (MODE == 1) ? H1 : N2;
    const float* A = (MODE == 1) ? g_z2 : g_z3;
    float* outp    = (MODE == 1) ? g_p1[blockIdx.y] : g_p2[blockIdx.y];

    __shared__ float As[MM_S][64][8];
    __shared__ float Bs[MM_S][8][136];  // +8 pad -> conflict-free frag loads

    int tid = threadIdx.x;
    int n0  = blockIdx.x * 128;
    int nsp = gridDim.y, sp = blockIdx.y;
    int tot = K / 8;
    int per = tot / nsp, rem = tot % nsp;
    int ks  = sp * per + min(sp, rem);
    int cnt = per + (sp < rem ? 1 : 0);

    int lane = tid & 31, wp = tid >> 5;
    int wm = wp >> 1, wn = wp & 1;
    int gq = lane >> 2, tq = lane & 3;

    int ar = tid >> 1, ac = (tid & 1) * 4;       // A staging coords
    int br = tid >> 5, bc = (tid & 31) * 4;      // B staging coords (2 chunks/thread)

    auto issue = [&](int st, int ki) {
        int kk = (ks + ki) * 8;
        cp16(sptr(&As[st][ar][ac]), A + ar * K + kk + ac);
        cp16(sptr(&Bs[st][br][bc]),     W + (size_t)(kk + br)     * NOUT + n0 + bc);
        cp16(sptr(&Bs[st][br + 4][bc]), W + (size_t)(kk + br + 4) * NOUT + n0 + bc);
    };

    float C[2][8][4] = {};

    for (int p = 0; p < MM_S - 1; p++) {
        if (p < cnt) issue(p, p);
        asm volatile("cp.async.commit_group;");
    }

    for (int i = 0; i < cnt; i++) {
        asm volatile("cp.async.wait_group %0;" :: "n"(MM_S - 2));
        __syncthreads();
        int st = i % MM_S;
        uint32_t a[2][4], b[8][2];
#pragma unroll
        for (int mi = 0; mi < 2; mi++) {
            int r = wm * 32 + mi * 16 + gq;
            a[mi][0] = __float_as_uint(As[st][r][tq]);
            a[mi][1] = __float_as_uint(As[st][r + 8][tq]);
            a[mi][2] = __float_as_uint(As[st][r][tq + 4]);
            a[mi][3] = __float_as_uint(As[st][r + 8][tq + 4]);
        }
#pragma unroll
        for (int ni = 0; ni < 8; ni++) {
            int c = wn * 64 + ni * 8 + gq;
            b[ni][0] = __float_as_uint(Bs[st][tq][c]);
            b[ni][1] = __float_as_uint(Bs[st][tq + 4][c]);
        }
#pragma unroll
        for (int mi = 0; mi < 2; mi++)
#pragma unroll
            for (int ni = 0; ni < 8; ni++)
                mma8(C[mi][ni], a[mi], b[ni]);
        int nx = i + MM_S - 1;
        if (nx < cnt) issue(nx % MM_S, nx);
        asm volatile("cp.async.commit_group;");
    }

    // write split-K partials (no atomics; epilogue sums)
#pragma unroll
    for (int mi = 0; mi < 2; mi++)
#pragma unroll
        for (int ni = 0; ni < 8; ni++) {
            int r = wm * 32 + mi * 16 + gq;
            int c = n0 + wn * 64 + ni * 8 + 2 * tq;
            float2 v0 = make_float2(C[mi][ni][0], C[mi][ni][1]);
            float2 v1 = make_float2(C[mi][ni][2], C[mi][ni][3]);
            *(float2*)&outp[(size_t)r * NOUT + c]       = v0;
            *(float2*)&outp[(size_t)(r + 8) * NOUT + c] = v1;
        }
}

// ---------------- epilogues ----------------
__global__ void k_epi1(const float* __restrict__ b1) {
    int i = blockIdx.x * 256 + threadIdx.x;
    if (i < NG * H1) {
        float v = g_p1[0][i] + g_p1[1][i] + g_p1[2][i] + b1[i % H1];
        g_z3[i] = fmaxf(v, 0.f);
    }
}
__global__ void k_epi2(const float* __restrict__ b2, float* __restrict__ out) {
    int i = blockIdx.x * 256 + threadIdx.x;
    if (i < NG * N2) {
        float v = g_p2[0][i] + g_p2[1][i] + g_p2[2][i] + g_p2[3][i] + g_p2[4][i] + g_p2[5][i]
                + b2[i % N2];
        out[i] = 1.f / (1.f + expf(-v));
    }
}

// ---------------- launch ----------------
extern "C" void kernel_launch(void* const* d_in, const int* in_sizes, int n_in,
                              void* d_out, int out_size) {
    const float* x  = (const float*)d_in[0];
    const int*   ei = (const int*)  d_in[1];
    const float* Wg = (const float*)d_in[2];
    const float* bg = (const float*)d_in[3];
    const float* W1 = (const float*)d_in[4];
    const float* b1 = (const float*)d_in[5];
    const float* W2 = (const float*)d_in[6];
    const float* b2 = (const float*)d_in[7];
    float* out = (float*)d_out;

    k_clear <<<20, 256>>>();
    k_xwg   <<<160, 256>>>(x, Wg);
    k_deg   <<<640, 256>>>(ei);
    k_scan  <<<1, 1024>>>();
    k_csr   <<<640, 256>>>(ei);
    k_gather<<<640, 256>>>(bg);
    k_outer <<<64, 256>>>();
    k_mm<1> <<<dim3(100, 3), 128>>>(W1);   // 300 CTAs ~ 2/SM
    k_epi1  <<<(NG * H1 + 255) / 256, 256>>>(b1);
    k_mm<2> <<<dim3(50, 6), 128>>>(W2);    // 300 CTAs ~ 2/SM
    k_epi2  <<<(NG * N2 + 255) / 256, 256>>>(b2, out);
}

// round 7
// speedup vs baseline: 1.1120x; 1.1120x over previous
#include <cuda_runtime.h>
#include <cstdint>

#define N_NODES 5120
#define N_EDGES 163840
#define TBLD    256
#define LAT     128
#define NG      64
#define NN      80
#define N2      6400
#define H1      12800

// ---------------- scratch (no allocs allowed) ----------------
__device__ __align__(128) float g_h [N_NODES * LAT];
__device__ __align__(128) float g_z [N_NODES * LAT];
__device__ __align__(128) float g_z2[NG * N2];
__device__ __align__(128) float g_z3[NG * H1];
__device__ __align__(128) float g_p1[6][NG * H1];    // GEMM1 split-K partials
__device__ __align__(128) float g_p2[12][NG * N2];   // GEMM2 split-K partials
__device__ int   g_deg[N_NODES];
__device__ int   g_cur[N_NODES];
__device__ int   g_row[N_NODES];
__device__ float g_dinv[N_NODES];
__device__ int   g_csr[N_EDGES];

// ---------------- stage 1: clear counters + h = x @ Wg (merged) --------------
__global__ void k_prep(const float* __restrict__ x, const float* __restrict__ Wg) {
    if (blockIdx.x >= 160) {   // clear part
        int i = (blockIdx.x - 160) * 256 + threadIdx.x;
        if (i < N_NODES) { g_deg[i] = 0; g_cur[i] = 0; }
        return;
    }
    __shared__ float Xs[32][33];
    __shared__ float Ws[32][128];
    int tid = threadIdx.x;
    int m0  = blockIdx.x * 32;
    int tm  = (tid >> 5) * 4;
    int tn  = (tid & 31) * 4;
    float acc[4][4] = {};
    for (int k0 = 0; k0 < TBLD; k0 += 32) {
        int r = tid >> 3, c = (tid & 7) * 4;
        float4 xv = *(const float4*)&x[(m0 + r) * TBLD + k0 + c];
        Xs[r][c] = xv.x; Xs[r][c + 1] = xv.y; Xs[r][c + 2] = xv.z; Xs[r][c + 3] = xv.w;
#pragma unroll
        for (int i = 0; i < 4; i++) {
            int idx = tid + i * 256;
            int wr = idx >> 5, wc = (idx & 31) * 4;
            *(float4*)&Ws[wr][wc] = *(const float4*)&Wg[(k0 + wr) * LAT + wc];
        }
        __syncthreads();
#pragma unroll
        for (int kk = 0; kk < 32; kk++) {
            float a0 = Xs[tm][kk], a1 = Xs[tm + 1][kk], a2 = Xs[tm + 2][kk], a3 = Xs[tm + 3][kk];
            float4 bv = *(float4*)&Ws[kk][tn];
            acc[0][0] += a0 * bv.x; acc[0][1] += a0 * bv.y; acc[0][2] += a0 * bv.z; acc[0][3] += a0 * bv.w;
            acc[1][0] += a1 * bv.x; acc[1][1] += a1 * bv.y; acc[1][2] += a1 * bv.z; acc[1][3] += a1 * bv.w;
            acc[2][0] += a2 * bv.x; acc[2][1] += a2 * bv.y; acc[2][2] += a2 * bv.z; acc[2][3] += a2 * bv.w;
            acc[3][0] += a3 * bv.x; acc[3][1] += a3 * bv.y; acc[3][2] += a3 * bv.z; acc[3][3] += a3 * bv.w;
        }
        __syncthreads();
    }
#pragma unroll
    for (int i = 0; i < 4; i++) {
        float4 v = make_float4(acc[i][0], acc[i][1], acc[i][2], acc[i][3]);
        *(float4*)&g_h[(m0 + tm + i) * LAT + tn] = v;
    }
}

// ---------------- stage 2: degree histogram over dst ----------------
__global__ void k_deg(const int* __restrict__ ei) {
    int e = blockIdx.x * blockDim.x + threadIdx.x;
    if (e < N_EDGES) atomicAdd(&g_deg[ei[N_EDGES + e]], 1);
}

// ---------------- stage 3: exclusive scan (shuffle) -> rowstart, dinv --------
__global__ void k_scan() {
    int tid = threadIdx.x, lane = tid & 31, wd = tid >> 5;
    int base = tid * 5;
    int d[5]; int s = 0;
#pragma unroll
    for (int i = 0; i < 5; i++) { d[i] = g_deg[base + i]; s += d[i]; }
    int tot = s;
#pragma unroll
    for (int off = 1; off < 32; off <<= 1) {
        int v = __shfl_up_sync(0xffffffffu, s, off);
        if (lane >= off) s += v;
    }
    __shared__ int ws[32];
    if (lane == 31) ws[wd] = s;
    __syncthreads();
    if (wd == 0) {
        int v = ws[lane];
#pragma unroll
        for (int off = 1; off < 32; off <<= 1) {
            int u = __shfl_up_sync(0xffffffffu, v, off);
            if (lane >= off) v += u;
        }
        ws[lane] = v;
    }
    __syncthreads();
    int pre = s - tot + (wd > 0 ? ws[wd - 1] : 0);
#pragma unroll
    for (int i = 0; i < 5; i++) {
        g_row[base + i]  = pre;
        pre += d[i];
        g_dinv[base + i] = d[i] > 0 ? rsqrtf((float)d[i]) : 0.f;
    }
}

// ---------------- stage 4: CSR fill ----------------
__global__ void k_csr(const int* __restrict__ ei) {
    int e = blockIdx.x * blockDim.x + threadIdx.x;
    if (e < N_EDGES) {
        int s = ei[e];
        int d = ei[N_EDGES + e];
        int p = atomicAdd(&g_cur[d], 1);
        g_csr[g_row[d] + p] = s;
    }
}

// ---------------- stage 5: gather-aggregate + bias + relu ----------------
__global__ void k_gather(const float* __restrict__ bg) {
    int node = blockIdx.x * 8 + (threadIdx.x >> 5);
    int lane = threadIdx.x & 31;
    int start = g_row[node];
    int cnt   = g_deg[node];
    float dd  = g_dinv[node];
    float4 acc = {0.f, 0.f, 0.f, 0.f};
    const float4* h4 = (const float4*)g_h;
    for (int j = 0; j < cnt; j++) {
        int s  = g_csr[start + j];
        float w = dd * g_dinv[s];
        float4 hv = h4[s * 32 + lane];
        acc.x += w * hv.x; acc.y += w * hv.y; acc.z += w * hv.z; acc.w += w * hv.w;
    }
    float4 bv = ((const float4*)bg)[lane];
    acc.x = fmaxf(acc.x + bv.x, 0.f);
    acc.y = fmaxf(acc.y + bv.y, 0.f);
    acc.z = fmaxf(acc.z + bv.z, 0.f);
    acc.w = fmaxf(acc.w + bv.w, 0.f);
    ((float4*)g_z)[node * 32 + lane] = acc;
}

// ---------------- stage 6: per-graph outer product z z^T ----------------
__global__ void k_outer() {
    __shared__ float Zs[NN][LAT + 1];
    int b = blockIdx.x, tid = threadIdx.x;
#pragma unroll
    for (int i = 0; i < 40; i++) {
        int idx = tid + i * 256;
        Zs[idx >> 7][idx & 127] = g_z[b * NN * LAT + idx];
    }
    __syncthreads();
    int rn = (tid >> 4) * 5;
    int rm = (tid & 15) * 5;
    float acc[5][5] = {};
    for (int l = 0; l < LAT; l++) {
        float a[5], bb[5];
#pragma unroll
        for (int i = 0; i < 5; i++) a[i]  = Zs[rn + i][l];
#pragma unroll
        for (int j = 0; j < 5; j++) bb[j] = Zs[rm + j][l];
#pragma unroll
        for (int i = 0; i < 5; i++)
#pragma unroll
            for (int j = 0; j < 5; j++) acc[i][j] += a[i] * bb[j];
    }
#pragma unroll
    for (int i = 0; i < 5; i++)
#pragma unroll
        for (int j = 0; j < 5; j++)
            g_z2[b * N2 + (rn + i) * NN + (rm + j)] = acc[i][j];
}

// ======================= tf32 mma.sync GEMM ==========================
__device__ __forceinline__ uint32_t sptr(const void* p) {
    return (uint32_t)__cvta_generic_to_shared(p);
}
__device__ __forceinline__ void cp16(uint32_t s, const void* g) {
    asm volatile("cp.async.cg.shared.global [%0], [%1], 16;" :: "r"(s), "l"(g));
}
__device__ __forceinline__ void mma8(float* c, const uint32_t* a, const uint32_t* b) {
    asm volatile(
        "mma.sync.aligned.m16n8k8.row.col.f32.tf32.tf32.f32 "
        "{%0,%1,%2,%3}, {%4,%5,%6,%7}, {%8,%9}, {%0,%1,%2,%3};"
        : "+f"(c[0]), "+f"(c[1]), "+f"(c[2]), "+f"(c[3])
        : "r"(a[0]), "r"(a[1]), "r"(a[2]), "r"(a[3]), "r"(b[0]), "r"(b[1]));
}

// smem layout (floats):
//   As: 3 stages x 64 rows x 20 (16 used + 4 pad)  -> 3840 floats
//   Bs: 3 stages x 16 rows x 264 (256 used + 8 pad)-> 12672 floats
#define A_ROW   20
#define A_STG   (64 * A_ROW)          // 1280
#define B_ROW   264
#define B_STG   (16 * B_ROW)          // 4224
#define B_OFF   (3 * A_STG)           // Bs start (floats)
#define MM_SMEM ((3 * A_STG + 3 * B_STG) * 4)   // 66048 bytes

// CTA: 64(M) x 256(N) tile, 8 warps (2x4), warp tile 32x64.
// K_CHUNK = 16 per stage, 3-stage cp.async ring (barrier every 16 K).
template<int MODE>
__global__ __launch_bounds__(256, 2) void k_mm(const float* __restrict__ W) {
    constexpr int K    = (MODE == 1) ? N2 : H1;
    constexpr int NOUT = (MODE == 1) ? H1 : N2;
    constexpr int NSPL = (MODE == 1) ? 6 : 12;
    const float* A = (MODE == 1) ? g_z2 : g_z3;
    float* outp    = (MODE == 1) ? g_p1[blockIdx.y] : g_p2[blockIdx.y];

    extern __shared__ float sm[];
    float* As = sm;
    float* Bs = sm + B_OFF;

    const int tid = threadIdx.x;
    const int n0  = blockIdx.x * 256;
    const int sp  = blockIdx.y;

    constexpr int TOT = K / 16;
    constexpr int per = TOT / NSPL, rem = TOT % NSPL;
    const int ks0 = sp * per + min(sp, rem);
    const int cnt = per + (sp < rem ? 1 : 0);

    const int lane = tid & 31, wp = tid >> 5;
    const int wm = wp >> 2, wn = wp & 3;      // 2 x 4 warp grid
    const int gq = lane >> 2, tq = lane & 3;

    // A staging: 1 cp16/thread: row = tid>>2, 16B chunk = tid&3
    const int a_r = tid >> 2, a_c4 = (tid & 3) * 4;
    const uint32_t a_dst0 = sptr(As) + (uint32_t)(a_r * A_ROW + a_c4) * 4;
    // B staging: 4 cp16/thread
    const uint32_t b_base = sptr(Bs);

    auto issue = [&](int st, int ki) {
        int kk = (ks0 + ki) * 16;
        cp16(a_dst0 + (uint32_t)(st * A_STG) * 4, A + (size_t)a_r * K + kk + a_c4);
#pragma unroll
        for (int q = 0; q < 4; q++) {
            int id = tid + q * 256;
            int r  = id >> 6, c4 = (id & 63) * 4;
            cp16(b_base + (uint32_t)(st * B_STG + r * B_ROW + c4) * 4,
                 W + (size_t)(kk + r) * NOUT + n0 + c4);
        }
    };

    float C[2][8][4] = {};

    issue(0, 0); asm volatile("cp.async.commit_group;");
    if (cnt > 1) issue(1, 1);
    asm volatile("cp.async.commit_group;");

    for (int i = 0; i < cnt; i++) {
        asm volatile("cp.async.wait_group 1;");
        __syncthreads();
        const int st = i % 3;
        const float* as = As + st * A_STG;
        const float* bs = Bs + st * B_STG;
#pragma unroll
        for (int s8 = 0; s8 < 2; s8++) {
            uint32_t a[2][4], b[8][2];
            int kc = 8 * s8;
#pragma unroll
            for (int mi = 0; mi < 2; mi++) {
                int r = wm * 32 + mi * 16 + gq;
                a[mi][0] = __float_as_uint(as[r * A_ROW + kc + tq]);
                a[mi][1] = __float_as_uint(as[(r + 8) * A_ROW + kc + tq]);
                a[mi][2] = __float_as_uint(as[r * A_ROW + kc + tq + 4]);
                a[mi][3] = __float_as_uint(as[(r + 8) * A_ROW + kc + tq + 4]);
            }
#pragma unroll
            for (int ni = 0; ni < 8; ni++) {
                int c = wn * 64 + ni * 8 + gq;
                b[ni][0] = __float_as_uint(bs[(kc + tq) * B_ROW + c]);
                b[ni][1] = __float_as_uint(bs[(kc + tq + 4) * B_ROW + c]);
            }
#pragma unroll
            for (int mi = 0; mi < 2; mi++)
#pragma unroll
                for (int ni = 0; ni < 8; ni++)
                    mma8(C[mi][ni], a[mi], b[ni]);
        }
        int nx = i + 2;
        if (nx < cnt) issue(nx % 3, nx);
        asm volatile("cp.async.commit_group;");
    }

    // write split-K partials (summed in epilogue)
#pragma unroll
    for (int mi = 0; mi < 2; mi++)
#pragma unroll
        for (int ni = 0; ni < 8; ni++) {
            int r = wm * 32 + mi * 16 + gq;
            int c = n0 + wn * 64 + ni * 8 + 2 * tq;
            *(float2*)&outp[(size_t)r * NOUT + c]       = make_float2(C[mi][ni][0], C[mi][ni][1]);
            *(float2*)&outp[(size_t)(r + 8) * NOUT + c] = make_float2(C[mi][ni][2], C[mi][ni][3]);
        }
}

// ---------------- epilogues (float4, sum partials + bias + act) --------------
__global__ void k_epi1(const float* __restrict__ b1) {
    int g = blockIdx.x * 256 + threadIdx.x;      // float4 index
    int e = g * 4;
    float4 v = *(const float4*)&g_p1[0][e];
#pragma unroll
    for (int s = 1; s < 6; s++) {
        float4 p = *(const float4*)&g_p1[s][e];
        v.x += p.x; v.y += p.y; v.z += p.z; v.w += p.w;
    }
    float4 bb = *(const float4*)&b1[e % H1];
    v.x = fmaxf(v.x + bb.x, 0.f); v.y = fmaxf(v.y + bb.y, 0.f);
    v.z = fmaxf(v.z + bb.z, 0.f); v.w = fmaxf(v.w + bb.w, 0.f);
    *(float4*)&g_z3[e] = v;
}
__global__ void k_epi2(const float* __restrict__ b2, float* __restrict__ out) {
    int g = blockIdx.x * 256 + threadIdx.x;
    int e = g * 4;
    float4 v = *(const float4*)&g_p2[0][e];
#pragma unroll
    for (int s = 1; s < 12; s++) {
        float4 p = *(const float4*)&g_p2[s][e];
        v.x += p.x; v.y += p.y; v.z += p.z; v.w += p.w;
    }
    float4 bb = *(const float4*)&b2[e % N2];
    v.x += bb.x; v.y += bb.y; v.z += bb.z; v.w += bb.w;
    float4 o;
    o.x = 1.f / (1.f + __expf(-v.x));
    o.y = 1.f / (1.f + __expf(-v.y));
    o.z = 1.f / (1.f + __expf(-v.z));
    o.w = 1.f / (1.f + __expf(-v.w));
    *(float4*)&out[e] = o;
}

// ---------------- launch ----------------
extern "C" void kernel_launch(void* const* d_in, const int* in_sizes, int n_in,
                              void* d_out, int out_size) {
    const float* x  = (const float*)d_in[0];
    const int*   ei = (const int*)  d_in[1];
    const float* Wg = (const float*)d_in[2];
    const float* bg = (const float*)d_in[3];
    const float* W1 = (const float*)d_in[4];
    const float* b1 = (const float*)d_in[5];
    const float* W2 = (const float*)d_in[6];
    const float* b2 = (const float*)d_in[7];
    float* out = (float*)d_out;

    static bool attr_done = false;
    if (!attr_done) {
        cudaFuncSetAttribute(k_mm<1>, cudaFuncAttributeMaxDynamicSharedMemorySize, MM_SMEM);
        cudaFuncSetAttribute(k_mm<2>, cudaFuncAttributeMaxDynamicSharedMemorySize, MM_SMEM);
        attr_done = true;
    }

    k_prep  <<<180, 256>>>(x, Wg);
    k_deg   <<<640, 256>>>(ei);
    k_scan  <<<1, 1024>>>();
    k_csr   <<<640, 256>>>(ei);
    k_gather<<<640, 256>>>(bg);
    k_outer <<<64, 256>>>();
    k_mm<1> <<<dim3(50, 6),  256, MM_SMEM>>>(W1);   // 300 CTAs, 2/SM
    k_epi1  <<<NG * H1 / 1024, 256>>>(b1);
    k_mm<2> <<<dim3(25, 12), 256, MM_SMEM>>>(W2);   // 300 CTAs, 2/SM
    k_epi2  <<<NG * N2 / 1024, 256>>>(b2, out);
}